// round 1
// baseline (speedup 1.0000x reference)
#include <cuda_runtime.h>
#include <math.h>

#define BB 2
#define SS 2048
#define DM 1024
#define NH 16
#define DKK 64
#define DFF 4096
#define MT (BB*SS)   // 4096 tokens

// ---------------- scratch (__device__ globals; no allocations) ----------------
__device__ float g_xn [(size_t)MT*DM];        // rmsnorm output (reused)
__device__ float g_lin[(size_t)3*MT*DM];      // q/k/v linear outputs (pre-rope)
__device__ float g_q  [(size_t)MT*DM];        // [b,h,s,dk]
__device__ float g_k  [(size_t)MT*DM];
__device__ float g_v  [(size_t)MT*DM];
__device__ float g_att[(size_t)MT*DM];        // attention out, [b,s,d]
__device__ float g_x1 [(size_t)MT*DM];        // residual-1 result
__device__ float g_a  [(size_t)MT*DFF];       // ffn a (then h)
__device__ float g_g  [(size_t)MT*DFF];       // ffn gate

// ---------------- rmsnorm: one row per block ----------------
__global__ void rmsnorm_k(const float* __restrict__ x, const float* __restrict__ w,
                          float* __restrict__ out) {
    int row = blockIdx.x;
    int t = threadIdx.x;  // 256 threads, DM/4 = 256 float4
    float4 xv = ((const float4*)(x + (size_t)row*DM))[t];
    float s = xv.x*xv.x + xv.y*xv.y + xv.z*xv.z + xv.w*xv.w;
    #pragma unroll
    for (int o = 16; o > 0; o >>= 1) s += __shfl_xor_sync(0xffffffffu, s, o);
    __shared__ float ws[8];
    __shared__ float s_inv;
    if ((t & 31) == 0) ws[t >> 5] = s;
    __syncthreads();
    if (t == 0) {
        float tot = 0.f;
        #pragma unroll
        for (int i = 0; i < 8; i++) tot += ws[i];
        s_inv = rsqrtf(tot / (float)DM + 1e-5f);
    }
    __syncthreads();
    float inv = s_inv;
    float4 wv = ((const float4*)w)[t];
    float4 ov;
    ov.x = xv.x*inv*wv.x; ov.y = xv.y*inv*wv.y;
    ov.z = xv.z*inv*wv.z; ov.w = xv.w*inv*wv.w;
    ((float4*)(out + (size_t)row*DM))[t] = ov;
}

// ---------------- SGEMM: C[M,N] = A[M,K] * B[N,K]^T (+ optional residual R) ----------------
// 128x128 tile, BK=16, 256 threads, 8x8 microtile per thread.
__global__ void __launch_bounds__(256) sgemm_nt(
    const float* __restrict__ A, const float* __restrict__ B,
    const float* __restrict__ R, float* __restrict__ C,
    int M, int N, int K)
{
    __shared__ float As[16][132];
    __shared__ float Bs[16][132];
    const int tid = threadIdx.x;
    const int bm = blockIdx.y * 128, bn = blockIdx.x * 128;
    const int tx = tid & 15, ty = tid >> 4;
    const int lr = tid >> 2;        // 0..63
    const int lc = (tid & 3) * 4;   // 0,4,8,12

    float acc[8][8];
    #pragma unroll
    for (int i = 0; i < 8; i++)
        #pragma unroll
        for (int j = 0; j < 8; j++) acc[i][j] = 0.f;

    for (int k0 = 0; k0 < K; k0 += 16) {
        #pragma unroll
        for (int h = 0; h < 2; h++) {
            int r = lr + h * 64;
            float4 av = *(const float4*)(A + (size_t)(bm + r)*K + k0 + lc);
            As[lc+0][r] = av.x; As[lc+1][r] = av.y; As[lc+2][r] = av.z; As[lc+3][r] = av.w;
            float4 bv = *(const float4*)(B + (size_t)(bn + r)*K + k0 + lc);
            Bs[lc+0][r] = bv.x; Bs[lc+1][r] = bv.y; Bs[lc+2][r] = bv.z; Bs[lc+3][r] = bv.w;
        }
        __syncthreads();
        #pragma unroll
        for (int k = 0; k < 16; k++) {
            float a[8], b[8];
            *(float4*)(a)   = *(const float4*)&As[k][ty*8];
            *(float4*)(a+4) = *(const float4*)&As[k][ty*8+4];
            *(float4*)(b)   = *(const float4*)&Bs[k][tx*8];
            *(float4*)(b+4) = *(const float4*)&Bs[k][tx*8+4];
            #pragma unroll
            for (int i = 0; i < 8; i++)
                #pragma unroll
                for (int j = 0; j < 8; j++)
                    acc[i][j] = fmaf(a[i], b[j], acc[i][j]);
        }
        __syncthreads();
    }

    #pragma unroll
    for (int i = 0; i < 8; i++) {
        size_t base = (size_t)(bm + ty*8 + i) * N + bn + tx*8;
        #pragma unroll
        for (int jj = 0; jj < 2; jj++) {
            float4 rv = make_float4(0.f, 0.f, 0.f, 0.f);
            if (R) rv = *(const float4*)(R + base + jj*4);
            float4 cv;
            cv.x = acc[i][jj*4+0] + rv.x;
            cv.y = acc[i][jj*4+1] + rv.y;
            cv.z = acc[i][jj*4+2] + rv.z;
            cv.w = acc[i][jj*4+3] + rv.w;
            *(float4*)(C + base + jj*4) = cv;
        }
    }
}

// ---------------- RoPE + head permute: [b,s,h*dk] -> [b,h,s,dk] ----------------
__global__ void rope_perm_k(const float* __restrict__ lin, const int* __restrict__ pos,
                            float* __restrict__ q, float* __restrict__ k,
                            float* __restrict__ v) {
    int idx = blockIdx.x * blockDim.x + threadIdx.x;
    if (idx >= MT * NH * (DKK/2)) return;
    int i  = idx & 31;            // freq pair index 0..31
    int hh = (idx >> 5) & (NH-1);
    int t  = idx >> 9;            // token 0..4095
    int b  = t >> 11;
    int s  = t & (SS - 1);
    size_t src = (size_t)t * DM + hh * DKK + 2*i;
    size_t dst = ((size_t)(b*NH + hh) * SS + s) * DKK + 2*i;
    // inv_freq = 10000^{-(2i)/64}, computed in double, rounded to fp32
    double ex = -((double)(2*i) / 64.0) * 9.210340371976184;  // ln(10000)
    float invf = (float)exp(ex);
    float ang = (float)pos[t] * invf;
    float sn, cs;
    sincosf(ang, &sn, &cs);
    float qe = lin[src], qo = lin[src+1];
    q[dst]   = qe*cs - qo*sn;
    q[dst+1] = qe*sn + qo*cs;
    const float* link = lin + (size_t)MT*DM;
    float ke = link[src], ko = link[src+1];
    k[dst]   = ke*cs - ko*sn;
    k[dst+1] = ke*sn + ko*cs;
    const float* linv = lin + (size_t)2*MT*DM;
    v[dst]   = linv[src];
    v[dst+1] = linv[src+1];
}

// ---------------- Flash attention, causal, 64x64 tiles, fp32 ----------------
// block: 256 threads; thread (tr,tc) owns rows tr*4..+3 and cols tc*4..+3.
#define ATT_SMEM (4*64*68*4)
__global__ void __launch_bounds__(256) attn_k(
    const float* __restrict__ Q, const float* __restrict__ Kg,
    const float* __restrict__ Vg, float* __restrict__ O)
{
    extern __shared__ float sm[];
    float* Qt = sm;             // [d][row], stride 68
    float* Kt = sm + 64*68;     // [d][key], stride 68
    float* Vs = sm + 2*64*68;   // [key][d], stride 68
    float* Ps = sm + 3*64*68;   // [row][key], stride 68
    const int qt = blockIdx.x, h = blockIdx.y, b = blockIdx.z;
    const int tid = threadIdx.x;
    const int tr = tid >> 4;        // 0..15
    const int tc = tid & 15;        // 0..15
    const int q0 = qt * 64;
    const float* Qh = Q  + (size_t)(b*NH + h) * SS * DKK;
    const float* Kh = Kg + (size_t)(b*NH + h) * SS * DKK;
    const float* Vh = Vg + (size_t)(b*NH + h) * SS * DKK;
    const int lr = tid >> 4;
    const int lc = (tid & 15) * 4;

    // load Q tile transposed into Qt[d][row]
    #pragma unroll
    for (int i = 0; i < 4; i++) {
        int rr = lr + i*16;
        float4 t4 = *(const float4*)(Qh + (size_t)(q0 + rr)*DKK + lc);
        Qt[(lc+0)*68 + rr] = t4.x; Qt[(lc+1)*68 + rr] = t4.y;
        Qt[(lc+2)*68 + rr] = t4.z; Qt[(lc+3)*68 + rr] = t4.w;
    }

    float o[4][4];
    #pragma unroll
    for (int i = 0; i < 4; i++)
        #pragma unroll
        for (int c = 0; c < 4; c++) o[i][c] = 0.f;
    float m[4], l[4];
    #pragma unroll
    for (int i = 0; i < 4; i++) { m[i] = -1e30f; l[i] = 0.f; }

    for (int kt = 0; kt <= qt; kt++) {
        int k0 = kt * 64;
        __syncthreads();   // previous iteration's Vs/Ps reads complete
        #pragma unroll
        for (int i = 0; i < 4; i++) {
            int rr = lr + i*16;
            float4 t4 = *(const float4*)(Kh + (size_t)(k0 + rr)*DKK + lc);
            Kt[(lc+0)*68 + rr] = t4.x; Kt[(lc+1)*68 + rr] = t4.y;
            Kt[(lc+2)*68 + rr] = t4.z; Kt[(lc+3)*68 + rr] = t4.w;
            float4 v4 = *(const float4*)(Vh + (size_t)(k0 + rr)*DKK + lc);
            *(float4*)&Vs[rr*68 + lc] = v4;
        }
        __syncthreads();

        // S = Q K^T (4x4 microtile per thread)
        float sv[4][4];
        #pragma unroll
        for (int i = 0; i < 4; i++)
            #pragma unroll
            for (int j = 0; j < 4; j++) sv[i][j] = 0.f;
        #pragma unroll 8
        for (int d = 0; d < DKK; d++) {
            float qa[4], kb[4];
            *(float4*)qa = *(const float4*)&Qt[d*68 + tr*4];
            *(float4*)kb = *(const float4*)&Kt[d*68 + tc*4];
            #pragma unroll
            for (int i = 0; i < 4; i++)
                #pragma unroll
                for (int j = 0; j < 4; j++)
                    sv[i][j] = fmaf(qa[i], kb[j], sv[i][j]);
        }

        // scale + causal mask
        #pragma unroll
        for (int i = 0; i < 4; i++) {
            int grow = q0 + tr*4 + i;
            #pragma unroll
            for (int j = 0; j < 4; j++) {
                int gcol = k0 + tc*4 + j;
                sv[i][j] = (gcol <= grow) ? sv[i][j] * 0.125f : -1e30f;
            }
        }

        // online softmax per row (reduce across the 16 tc lanes: same warp half)
        #pragma unroll
        for (int i = 0; i < 4; i++) {
            float rm = fmaxf(fmaxf(sv[i][0], sv[i][1]), fmaxf(sv[i][2], sv[i][3]));
            #pragma unroll
            for (int off = 1; off < 16; off <<= 1)
                rm = fmaxf(rm, __shfl_xor_sync(0xffffffffu, rm, off));
            float mn = fmaxf(m[i], rm);
            float alpha = __expf(m[i] - mn);
            float rs = 0.f;
            #pragma unroll
            for (int j = 0; j < 4; j++) {
                sv[i][j] = __expf(sv[i][j] - mn);
                rs += sv[i][j];
            }
            #pragma unroll
            for (int off = 1; off < 16; off <<= 1)
                rs += __shfl_xor_sync(0xffffffffu, rs, off);
            l[i] = l[i] * alpha + rs;
            m[i] = mn;
            #pragma unroll
            for (int c = 0; c < 4; c++) o[i][c] *= alpha;
            *(float4*)&Ps[(tr*4 + i)*68 + tc*4] =
                make_float4(sv[i][0], sv[i][1], sv[i][2], sv[i][3]);
        }
        __syncthreads();

        // O += P V
        #pragma unroll 4
        for (int j = 0; j < 64; j++) {
            float vb[4];
            *(float4*)vb = *(const float4*)&Vs[j*68 + tc*4];
            #pragma unroll
            for (int i = 0; i < 4; i++) {
                float p = Ps[(tr*4 + i)*68 + j];  // broadcast across tc
                #pragma unroll
                for (int c = 0; c < 4; c++)
                    o[i][c] = fmaf(p, vb[c], o[i][c]);
            }
        }
    }

    // epilogue: normalize and write [b, s, h*dk + d]
    #pragma unroll
    for (int i = 0; i < 4; i++) {
        float inv = 1.f / l[i];
        int row = q0 + tr*4 + i;
        float4 ov = make_float4(o[i][0]*inv, o[i][1]*inv, o[i][2]*inv, o[i][3]*inv);
        *(float4*)(O + (size_t)(b*SS + row)*DM + h*DKK + tc*4) = ov;
    }
}

// ---------------- silu(a) * g, vectorized ----------------
__global__ void silu_mul_k(float4* __restrict__ a, const float4* __restrict__ g, int n4) {
    int i = blockIdx.x * blockDim.x + threadIdx.x;
    if (i >= n4) return;
    float4 av = a[i], gv = g[i], r;
    r.x = (av.x / (1.f + __expf(-av.x))) * gv.x;
    r.y = (av.y / (1.f + __expf(-av.y))) * gv.y;
    r.z = (av.z / (1.f + __expf(-av.z))) * gv.z;
    r.w = (av.w / (1.f + __expf(-av.w))) * gv.w;
    a[i] = r;
}

// ---------------- launcher ----------------
extern "C" void kernel_launch(void* const* d_in, const int* in_sizes, int n_in,
                              void* d_out, int out_size) {
    const float* x   = (const float*)d_in[0];
    const int*   pos = (const int*)  d_in[1];
    const float* n1w = (const float*)d_in[2];
    const float* n2w = (const float*)d_in[3];
    const float* wq  = (const float*)d_in[4];
    const float* wk  = (const float*)d_in[5];
    const float* wv  = (const float*)d_in[6];
    const float* wo  = (const float*)d_in[7];
    const float* w1  = (const float*)d_in[8];
    const float* w2  = (const float*)d_in[9];
    const float* w3  = (const float*)d_in[10];
    float* out = (float*)d_out;

    float *xn, *lin, *q, *k, *v, *att, *x1, *a, *g;
    cudaGetSymbolAddress((void**)&xn,  g_xn);
    cudaGetSymbolAddress((void**)&lin, g_lin);
    cudaGetSymbolAddress((void**)&q,   g_q);
    cudaGetSymbolAddress((void**)&k,   g_k);
    cudaGetSymbolAddress((void**)&v,   g_v);
    cudaGetSymbolAddress((void**)&att, g_att);
    cudaGetSymbolAddress((void**)&x1,  g_x1);
    cudaGetSymbolAddress((void**)&a,   g_a);
    cudaGetSymbolAddress((void**)&g,   g_g);

    cudaFuncSetAttribute(attn_k, cudaFuncAttributeMaxDynamicSharedMemorySize, ATT_SMEM);

    // 1) rmsnorm 1
    rmsnorm_k<<<MT, 256>>>(x, n1w, xn);
    // 2) QKV projections
    sgemm_nt<<<dim3(DM/128, MT/128), 256>>>(xn, wq, nullptr, lin,                   MT, DM, DM);
    sgemm_nt<<<dim3(DM/128, MT/128), 256>>>(xn, wk, nullptr, lin + (size_t)MT*DM,   MT, DM, DM);
    sgemm_nt<<<dim3(DM/128, MT/128), 256>>>(xn, wv, nullptr, lin + (size_t)2*MT*DM, MT, DM, DM);
    // 3) rope + permute to [b,h,s,dk]
    rope_perm_k<<<(MT*NH*(DKK/2))/256, 256>>>(lin, pos, q, k, v);
    // 4) attention
    attn_k<<<dim3(SS/64, NH, BB), 256, ATT_SMEM>>>(q, k, v, att);
    // 5) output projection + residual
    sgemm_nt<<<dim3(DM/128, MT/128), 256>>>(att, wo, x, x1, MT, DM, DM);
    // 6) rmsnorm 2
    rmsnorm_k<<<MT, 256>>>(x1, n2w, xn);
    // 7) FFN up projections
    sgemm_nt<<<dim3(DFF/128, MT/128), 256>>>(xn, w1, nullptr, a, MT, DFF, DM);
    sgemm_nt<<<dim3(DFF/128, MT/128), 256>>>(xn, w3, nullptr, g, MT, DFF, DM);
    // 8) h = silu(a) * g
    silu_mul_k<<<(MT*DFF/4 + 255)/256, 256>>>((float4*)a, (const float4*)g, MT*DFF/4);
    // 9) down projection + residual -> output
    sgemm_nt<<<dim3(DM/128, MT/128), 256>>>(a, w2, x1, out, MT, DM, DFF);
}

// round 3
// speedup vs baseline: 2.3937x; 2.3937x over previous
#include <cuda_runtime.h>
#include <cuda_bf16.h>
#include <math.h>
#include <stdint.h>

#define BB 2
#define SS 2048
#define DM 1024
#define NH 16
#define DKK 64
#define DFF 4096
#define MT (BB*SS)   // 4096 tokens

// ---------------- scratch (__device__ globals; no allocations) ----------------
__device__ float g_xn [(size_t)MT*DM];
__device__ float g_lin[(size_t)3*MT*DM];
__device__ float g_q  [(size_t)MT*DM];
__device__ float g_k  [(size_t)MT*DM];
__device__ float g_v  [(size_t)MT*DM];
__device__ float g_att[(size_t)MT*DM];
__device__ float g_x1 [(size_t)MT*DM];
__device__ float g_a  [(size_t)MT*DFF];
__device__ float g_g  [(size_t)MT*DFF];

// ================= helpers =================
__device__ __forceinline__ uint32_t smem_u32(const void* p) {
    uint32_t a;
    asm("{ .reg .u64 t; cvta.to.shared.u64 t, %1; cvt.u32.u64 %0, t; }" : "=r"(a) : "l"(p));
    return a;
}
__device__ __forceinline__ void ldm_x4(uint32_t* r, uint32_t addr) {
    asm volatile("ldmatrix.sync.aligned.m8n8.x4.shared.b16 {%0,%1,%2,%3}, [%4];"
        : "=r"(r[0]),"=r"(r[1]),"=r"(r[2]),"=r"(r[3]) : "r"(addr));
}
__device__ __forceinline__ void mma_bf16(float* d,
        uint32_t a0, uint32_t a1, uint32_t a2, uint32_t a3,
        uint32_t b0, uint32_t b1) {
    asm volatile("mma.sync.aligned.m16n8k16.row.col.f32.bf16.bf16.f32 "
        "{%0,%1,%2,%3}, {%4,%5,%6,%7}, {%8,%9}, {%0,%1,%2,%3};"
        : "+f"(d[0]),"+f"(d[1]),"+f"(d[2]),"+f"(d[3])
        : "r"(a0),"r"(a1),"r"(a2),"r"(a3),"r"(b0),"r"(b1));
}

// split fp32x4 -> 4 bf16 hi (8B) + 4 bf16 lo (8B), store to smem
__device__ __forceinline__ void cvt_split8(uint32_t hi_addr, uint32_t lo_addr, float4 v) {
    __nv_bfloat162 h0 = __floats2bfloat162_rn(v.x, v.y);
    __nv_bfloat162 h1 = __floats2bfloat162_rn(v.z, v.w);
    uint32_t u0 = *reinterpret_cast<uint32_t*>(&h0);
    uint32_t u1 = *reinterpret_cast<uint32_t*>(&h1);
    float rx = v.x - __uint_as_float(u0 << 16);
    float ry = v.y - __uint_as_float(u0 & 0xffff0000u);
    float rz = v.z - __uint_as_float(u1 << 16);
    float rw = v.w - __uint_as_float(u1 & 0xffff0000u);
    __nv_bfloat162 l0 = __floats2bfloat162_rn(rx, ry);
    __nv_bfloat162 l1 = __floats2bfloat162_rn(rz, rw);
    uint32_t w0 = *reinterpret_cast<uint32_t*>(&l0);
    uint32_t w1 = *reinterpret_cast<uint32_t*>(&l1);
    asm volatile("st.shared.v2.b32 [%0], {%1, %2};" :: "r"(hi_addr), "r"(u0), "r"(u1));
    asm volatile("st.shared.v2.b32 [%0], {%1, %2};" :: "r"(lo_addr), "r"(w0), "r"(w1));
}

// ================= split-bf16 tensor-core GEMM (mma.sync) =================
// C[M,N] = A[M,K] * B[N,K]^T (+ optional residual R). fp32 in/out.
// 128x128 CTA tile, BK=32, double-buffered.
// smem row stride 80B (64B data + 16B pad) -> conflict-free ldmatrix.
#define BK 32
#define ROWB 80                    // bytes per row in smem
#define MATB (128*ROWB)            // 10240 B per matrix tile
#define STAGEB (4*MATB)            // A_hi, A_lo, B_hi, B_lo
#define GEMM_SMEM (2*STAGEB)       // 81920 B

__global__ void __launch_bounds__(256, 1) gemm_mma(
    const float* __restrict__ A, const float* __restrict__ B,
    const float* __restrict__ R, float* __restrict__ C,
    int M, int N, int K)
{
    extern __shared__ char smem[];
    const uint32_t sb = smem_u32(smem);
    const int tid = threadIdx.x;
    const int wid = tid >> 5, lane = tid & 31;
    const int bm = blockIdx.y * 128, bn = blockIdx.x * 128;
    const int wm = (wid & 1) * 64, wn = (wid >> 1) * 32;

    // ldmatrix address components
    const int a_r16 = lane & 15, a_kh = lane >> 4;            // A: row-in-16, k-half
    const int b_row = (lane & 7) + ((lane & 16) ? 8 : 0);     // B: row-in-16
    const int b_kh = (lane >> 3) & 1;

    // per-thread load mapping: 1024 float4 per matrix per stage, 4 per thread
    const int ld_row = tid >> 1;              // 0..127  (2 threads per row)
    const int ld_f4  = (tid & 1) * 4;         // f4 index 0 or 4; each thread does 4 consecutive? no:
    // simpler mapping: idx = tid + i*256, row = idx>>3, f4 = idx&7

    float acc[4][4][4];
    #pragma unroll
    for (int mi = 0; mi < 4; mi++)
        #pragma unroll
        for (int ni = 0; ni < 4; ni++)
            #pragma unroll
            for (int r = 0; r < 4; r++) acc[mi][ni][r] = 0.f;

    const int NC = K >> 5;  // K/32

    // ---- prologue: load + convert stage 0 ----
    {
        const float* At = A + (size_t)bm * K;
        const float* Bt = B + (size_t)bn * K;
        #pragma unroll
        for (int i = 0; i < 4; i++) {
            int idx = tid + i * 256;
            int row = idx >> 3, f4 = idx & 7;
            uint32_t off = (uint32_t)(row * ROWB + f4 * 8);
            float4 av = *(const float4*)(At + (size_t)row * K + f4 * 4);
            cvt_split8(sb + off, sb + MATB + off, av);
            float4 bv = *(const float4*)(Bt + (size_t)row * K + f4 * 4);
            cvt_split8(sb + 2*MATB + off, sb + 3*MATB + off, bv);
        }
    }
    __syncthreads();

    for (int c = 0; c < NC; c++) {
        const int stg = c & 1;
        const uint32_t base = sb + stg * STAGEB;

        // ---- issue next-stage global loads early ----
        float4 aw[4], bw[4];
        if (c + 1 < NC) {
            const float* At = A + (size_t)bm * K + (c + 1) * BK;
            const float* Bt = B + (size_t)bn * K + (c + 1) * BK;
            #pragma unroll
            for (int i = 0; i < 4; i++) {
                int idx = tid + i * 256;
                int row = idx >> 3, f4 = idx & 7;
                aw[i] = *(const float4*)(At + (size_t)row * K + f4 * 4);
                bw[i] = *(const float4*)(Bt + (size_t)row * K + f4 * 4);
            }
        }

        // ---- compute current stage ----
        #pragma unroll
        for (int kk = 0; kk < 2; kk++) {
            uint32_t ah[4][4], al[4][4], bh[2][4], bl[2][4];
            #pragma unroll
            for (int mi = 0; mi < 4; mi++) {
                uint32_t ad = base + (uint32_t)((wm + mi*16 + a_r16) * ROWB + kk*32 + a_kh*16);
                ldm_x4(ah[mi], ad);
                ldm_x4(al[mi], ad + MATB);
            }
            #pragma unroll
            for (int p = 0; p < 2; p++) {
                uint32_t bd = base + 2*MATB
                            + (uint32_t)((wn + p*16 + b_row) * ROWB + kk*32 + b_kh*16);
                ldm_x4(bh[p], bd);
                ldm_x4(bl[p], bd + MATB);
            }
            #pragma unroll
            for (int mi = 0; mi < 4; mi++) {
                #pragma unroll
                for (int ni = 0; ni < 4; ni++) {
                    const int p = ni >> 1, s = (ni & 1) * 2;
                    mma_bf16(acc[mi][ni], ah[mi][0], ah[mi][1], ah[mi][2], ah[mi][3],
                             bh[p][s], bh[p][s+1]);
                    mma_bf16(acc[mi][ni], ah[mi][0], ah[mi][1], ah[mi][2], ah[mi][3],
                             bl[p][s], bl[p][s+1]);
                    mma_bf16(acc[mi][ni], al[mi][0], al[mi][1], al[mi][2], al[mi][3],
                             bh[p][s], bh[p][s+1]);
                }
            }
        }

        // ---- convert + store next stage ----
        if (c + 1 < NC) {
            const uint32_t nb = sb + (stg ^ 1) * STAGEB;
            #pragma unroll
            for (int i = 0; i < 4; i++) {
                int idx = tid + i * 256;
                int row = idx >> 3, f4 = idx & 7;
                uint32_t off = (uint32_t)(row * ROWB + f4 * 8);
                cvt_split8(nb + off, nb + MATB + off, aw[i]);
                cvt_split8(nb + 2*MATB + off, nb + 3*MATB + off, bw[i]);
            }
        }
        __syncthreads();
    }

    // ---- epilogue ----
    const int g = lane >> 2, tg = lane & 3;
    #pragma unroll
    for (int mi = 0; mi < 4; mi++) {
        #pragma unroll
        for (int ni = 0; ni < 4; ni++) {
            int r0 = bm + wm + mi*16 + g;
            int c0 = bn + wn + ni*8 + tg*2;
            float* d = acc[mi][ni];
            if (R) {
                float2 rv0 = *(const float2*)(R + (size_t)r0 * N + c0);
                float2 rv1 = *(const float2*)(R + (size_t)(r0+8) * N + c0);
                *(float2*)(C + (size_t)r0 * N + c0)     = make_float2(d[0]+rv0.x, d[1]+rv0.y);
                *(float2*)(C + (size_t)(r0+8) * N + c0) = make_float2(d[2]+rv1.x, d[3]+rv1.y);
            } else {
                *(float2*)(C + (size_t)r0 * N + c0)     = make_float2(d[0], d[1]);
                *(float2*)(C + (size_t)(r0+8) * N + c0) = make_float2(d[2], d[3]);
            }
        }
    }
}

// ---------------- rmsnorm: one row per block ----------------
__global__ void rmsnorm_k(const float* __restrict__ x, const float* __restrict__ w,
                          float* __restrict__ out) {
    int row = blockIdx.x;
    int t = threadIdx.x;
    float4 xv = ((const float4*)(x + (size_t)row*DM))[t];
    float s = xv.x*xv.x + xv.y*xv.y + xv.z*xv.z + xv.w*xv.w;
    #pragma unroll
    for (int o = 16; o > 0; o >>= 1) s += __shfl_xor_sync(0xffffffffu, s, o);
    __shared__ float ws[8];
    __shared__ float s_inv;
    if ((t & 31) == 0) ws[t >> 5] = s;
    __syncthreads();
    if (t == 0) {
        float tot = 0.f;
        #pragma unroll
        for (int i = 0; i < 8; i++) tot += ws[i];
        s_inv = rsqrtf(tot / (float)DM + 1e-5f);
    }
    __syncthreads();
    float inv = s_inv;
    float4 wv = ((const float4*)w)[t];
    float4 ov;
    ov.x = xv.x*inv*wv.x; ov.y = xv.y*inv*wv.y;
    ov.z = xv.z*inv*wv.z; ov.w = xv.w*inv*wv.w;
    ((float4*)(out + (size_t)row*DM))[t] = ov;
}

// ---------------- RoPE + head permute ----------------
__global__ void rope_perm_k(const float* __restrict__ lin, const int* __restrict__ pos,
                            float* __restrict__ q, float* __restrict__ k,
                            float* __restrict__ v) {
    int idx = blockIdx.x * blockDim.x + threadIdx.x;
    if (idx >= MT * NH * (DKK/2)) return;
    int i  = idx & 31;
    int hh = (idx >> 5) & (NH-1);
    int t  = idx >> 9;
    int b  = t >> 11;
    int s  = t & (SS - 1);
    size_t src = (size_t)t * DM + hh * DKK + 2*i;
    size_t dst = ((size_t)(b*NH + hh) * SS + s) * DKK + 2*i;
    double ex = -((double)(2*i) / 64.0) * 9.210340371976184;
    float invf = (float)exp(ex);
    float ang = (float)pos[t] * invf;
    float sn, cs;
    sincosf(ang, &sn, &cs);
    float qe = lin[src], qo = lin[src+1];
    q[dst]   = qe*cs - qo*sn;
    q[dst+1] = qe*sn + qo*cs;
    const float* link = lin + (size_t)MT*DM;
    float ke = link[src], ko = link[src+1];
    k[dst]   = ke*cs - ko*sn;
    k[dst+1] = ke*sn + ko*cs;
    const float* linv = lin + (size_t)2*MT*DM;
    v[dst]   = linv[src];
    v[dst+1] = linv[src+1];
}

// ---------------- Flash attention, causal, 64x64 tiles, fp32 ----------------
#define ATT_SMEM (4*64*68*4)
__global__ void __launch_bounds__(256) attn_k(
    const float* __restrict__ Q, const float* __restrict__ Kg,
    const float* __restrict__ Vg, float* __restrict__ O)
{
    extern __shared__ float sm[];
    float* Qt = sm;
    float* Kt = sm + 64*68;
    float* Vs = sm + 2*64*68;
    float* Ps = sm + 3*64*68;
    const int qt = blockIdx.x, h = blockIdx.y, b = blockIdx.z;
    const int tid = threadIdx.x;
    const int tr = tid >> 4;
    const int tc = tid & 15;
    const int q0 = qt * 64;
    const float* Qh = Q  + (size_t)(b*NH + h) * SS * DKK;
    const float* Kh = Kg + (size_t)(b*NH + h) * SS * DKK;
    const float* Vh = Vg + (size_t)(b*NH + h) * SS * DKK;
    const int lr = tid >> 4;
    const int lc = (tid & 15) * 4;

    #pragma unroll
    for (int i = 0; i < 4; i++) {
        int rr = lr + i*16;
        float4 t4 = *(const float4*)(Qh + (size_t)(q0 + rr)*DKK + lc);
        Qt[(lc+0)*68 + rr] = t4.x; Qt[(lc+1)*68 + rr] = t4.y;
        Qt[(lc+2)*68 + rr] = t4.z; Qt[(lc+3)*68 + rr] = t4.w;
    }

    float o[4][4];
    #pragma unroll
    for (int i = 0; i < 4; i++)
        #pragma unroll
        for (int c = 0; c < 4; c++) o[i][c] = 0.f;
    float m[4], l[4];
    #pragma unroll
    for (int i = 0; i < 4; i++) { m[i] = -1e30f; l[i] = 0.f; }

    for (int kt = 0; kt <= qt; kt++) {
        int k0 = kt * 64;
        __syncthreads();
        #pragma unroll
        for (int i = 0; i < 4; i++) {
            int rr = lr + i*16;
            float4 t4 = *(const float4*)(Kh + (size_t)(k0 + rr)*DKK + lc);
            Kt[(lc+0)*68 + rr] = t4.x; Kt[(lc+1)*68 + rr] = t4.y;
            Kt[(lc+2)*68 + rr] = t4.z; Kt[(lc+3)*68 + rr] = t4.w;
            float4 v4 = *(const float4*)(Vh + (size_t)(k0 + rr)*DKK + lc);
            *(float4*)&Vs[rr*68 + lc] = v4;
        }
        __syncthreads();

        float sv[4][4];
        #pragma unroll
        for (int i = 0; i < 4; i++)
            #pragma unroll
            for (int j = 0; j < 4; j++) sv[i][j] = 0.f;
        #pragma unroll 8
        for (int d = 0; d < DKK; d++) {
            float qa[4], kb[4];
            *(float4*)qa = *(const float4*)&Qt[d*68 + tr*4];
            *(float4*)kb = *(const float4*)&Kt[d*68 + tc*4];
            #pragma unroll
            for (int i = 0; i < 4; i++)
                #pragma unroll
                for (int j = 0; j < 4; j++)
                    sv[i][j] = fmaf(qa[i], kb[j], sv[i][j]);
        }

        #pragma unroll
        for (int i = 0; i < 4; i++) {
            int grow = q0 + tr*4 + i;
            #pragma unroll
            for (int j = 0; j < 4; j++) {
                int gcol = k0 + tc*4 + j;
                sv[i][j] = (gcol <= grow) ? sv[i][j] * 0.125f : -1e30f;
            }
        }

        #pragma unroll
        for (int i = 0; i < 4; i++) {
            float rm = fmaxf(fmaxf(sv[i][0], sv[i][1]), fmaxf(sv[i][2], sv[i][3]));
            #pragma unroll
            for (int off = 1; off < 16; off <<= 1)
                rm = fmaxf(rm, __shfl_xor_sync(0xffffffffu, rm, off));
            float mn = fmaxf(m[i], rm);
            float alpha = __expf(m[i] - mn);
            float rs = 0.f;
            #pragma unroll
            for (int j = 0; j < 4; j++) {
                sv[i][j] = __expf(sv[i][j] - mn);
                rs += sv[i][j];
            }
            #pragma unroll
            for (int off = 1; off < 16; off <<= 1)
                rs += __shfl_xor_sync(0xffffffffu, rs, off);
            l[i] = l[i] * alpha + rs;
            m[i] = mn;
            #pragma unroll
            for (int c = 0; c < 4; c++) o[i][c] *= alpha;
            *(float4*)&Ps[(tr*4 + i)*68 + tc*4] =
                make_float4(sv[i][0], sv[i][1], sv[i][2], sv[i][3]);
        }
        __syncthreads();

        #pragma unroll 4
        for (int j = 0; j < 64; j++) {
            float vb[4];
            *(float4*)vb = *(const float4*)&Vs[j*68 + tc*4];
            #pragma unroll
            for (int i = 0; i < 4; i++) {
                float p = Ps[(tr*4 + i)*68 + j];
                #pragma unroll
                for (int c = 0; c < 4; c++)
                    o[i][c] = fmaf(p, vb[c], o[i][c]);
            }
        }
    }

    #pragma unroll
    for (int i = 0; i < 4; i++) {
        float inv = 1.f / l[i];
        int row = q0 + tr*4 + i;
        float4 ov = make_float4(o[i][0]*inv, o[i][1]*inv, o[i][2]*inv, o[i][3]*inv);
        *(float4*)(O + (size_t)(b*SS + row)*DM + h*DKK + tc*4) = ov;
    }
}

// ---------------- silu(a) * g, vectorized ----------------
__global__ void silu_mul_k(float4* __restrict__ a, const float4* __restrict__ g, int n4) {
    int i = blockIdx.x * blockDim.x + threadIdx.x;
    if (i >= n4) return;
    float4 av = a[i], gv = g[i], r;
    r.x = (av.x / (1.f + __expf(-av.x))) * gv.x;
    r.y = (av.y / (1.f + __expf(-av.y))) * gv.y;
    r.z = (av.z / (1.f + __expf(-av.z))) * gv.z;
    r.w = (av.w / (1.f + __expf(-av.w))) * gv.w;
    a[i] = r;
}

// ---------------- launcher ----------------
extern "C" void kernel_launch(void* const* d_in, const int* in_sizes, int n_in,
                              void* d_out, int out_size) {
    const float* x   = (const float*)d_in[0];
    const int*   pos = (const int*)  d_in[1];
    const float* n1w = (const float*)d_in[2];
    const float* n2w = (const float*)d_in[3];
    const float* wq  = (const float*)d_in[4];
    const float* wk  = (const float*)d_in[5];
    const float* wv  = (const float*)d_in[6];
    const float* wo  = (const float*)d_in[7];
    const float* w1  = (const float*)d_in[8];
    const float* w2  = (const float*)d_in[9];
    const float* w3  = (const float*)d_in[10];
    float* out = (float*)d_out;

    float *xn, *lin, *q, *k, *v, *att, *x1, *a, *g;
    cudaGetSymbolAddress((void**)&xn,  g_xn);
    cudaGetSymbolAddress((void**)&lin, g_lin);
    cudaGetSymbolAddress((void**)&q,   g_q);
    cudaGetSymbolAddress((void**)&k,   g_k);
    cudaGetSymbolAddress((void**)&v,   g_v);
    cudaGetSymbolAddress((void**)&att, g_att);
    cudaGetSymbolAddress((void**)&x1,  g_x1);
    cudaGetSymbolAddress((void**)&a,   g_a);
    cudaGetSymbolAddress((void**)&g,   g_g);

    cudaFuncSetAttribute(attn_k, cudaFuncAttributeMaxDynamicSharedMemorySize, ATT_SMEM);
    cudaFuncSetAttribute(gemm_mma, cudaFuncAttributeMaxDynamicSharedMemorySize, GEMM_SMEM);

    // 1) rmsnorm 1
    rmsnorm_k<<<MT, 256>>>(x, n1w, xn);
    // 2) QKV projections (tensor core)
    gemm_mma<<<dim3(DM/128, MT/128), 256, GEMM_SMEM>>>(xn, wq, nullptr, lin,                   MT, DM, DM);
    gemm_mma<<<dim3(DM/128, MT/128), 256, GEMM_SMEM>>>(xn, wk, nullptr, lin + (size_t)MT*DM,   MT, DM, DM);
    gemm_mma<<<dim3(DM/128, MT/128), 256, GEMM_SMEM>>>(xn, wv, nullptr, lin + (size_t)2*MT*DM, MT, DM, DM);
    // 3) rope + permute
    rope_perm_k<<<(MT*NH*(DKK/2))/256, 256>>>(lin, pos, q, k, v);
    // 4) attention
    attn_k<<<dim3(SS/64, NH, BB), 256, ATT_SMEM>>>(q, k, v, att);
    // 5) output projection + residual
    gemm_mma<<<dim3(DM/128, MT/128), 256, GEMM_SMEM>>>(att, wo, x, x1, MT, DM, DM);
    // 6) rmsnorm 2
    rmsnorm_k<<<MT, 256>>>(x1, n2w, xn);
    // 7) FFN up
    gemm_mma<<<dim3(DFF/128, MT/128), 256, GEMM_SMEM>>>(xn, w1, nullptr, a, MT, DFF, DM);
    gemm_mma<<<dim3(DFF/128, MT/128), 256, GEMM_SMEM>>>(xn, w3, nullptr, g, MT, DFF, DM);
    // 8) h = silu(a) * g
    silu_mul_k<<<(MT*DFF/4 + 255)/256, 256>>>((float4*)a, (const float4*)g, MT*DFF/4);
    // 9) down projection + residual -> output
    gemm_mma<<<dim3(DM/128, MT/128), 256, GEMM_SMEM>>>(a, w2, x1, out, MT, DM, DFF);
}